// round 2
// baseline (speedup 1.0000x reference)
#include <cuda_runtime.h>

// Problem constants (fixed by the dataset)
#define N_NODES 50000
#define N_EDGES 625000
#define D_FEAT  128
#define K_HOPS  10

// ---------------------------------------------------------------------------
// Scratch (device globals — no allocation allowed anywhere)
// ---------------------------------------------------------------------------
__device__ float g_h0[N_NODES * D_FEAT];   // ping  (h_k for odd k)
__device__ float g_h1[N_NODES * D_FEAT];   // pong  (h_k for even k)
__device__ int   g_deg[N_NODES];
__device__ int   g_rowptr[N_NODES + 1];
__device__ int   g_cursor[N_NODES];
__device__ int   g_col[N_EDGES];
__device__ float g_w[K_HOPS + 1];
__device__ int   g_is64;

// ---------------------------------------------------------------------------
// 0) detect edge_index dtype (int32 vs int64) at runtime.
//    If data is int32, reading it as int64 packs two random values in
//    [0, 50000) into one word -> result >= 2^32 unless the high half is 0
//    (prob ~2e-5 per sample; 64 samples make a false positive impossible
//    in practice).
// ---------------------------------------------------------------------------
__global__ void detect_dtype_kernel(const void* ei) {
    if (threadIdx.x == 0 && blockIdx.x == 0) {
        const long long* p = (const long long*)ei;
        int is64 = 1;
        for (int i = 0; i < 64; i++) {
            long long v = p[i];
            if (v < 0 || v >= (long long)N_NODES) { is64 = 0; break; }
        }
        g_is64 = is64;
    }
}

__device__ __forceinline__ int load_edge(const void* ei, int idx, int is64) {
    if (is64) return (int)((const long long*)ei)[idx];
    return ((const int*)ei)[idx];
}

// ---------------------------------------------------------------------------
// 1) softmax of the 11 attention logits (trivial, 1 thread)
// ---------------------------------------------------------------------------
__global__ void softmax_att_kernel(const float* __restrict__ att) {
    if (threadIdx.x == 0 && blockIdx.x == 0) {
        float m = -1e30f;
        for (int i = 0; i <= K_HOPS; i++) m = fmaxf(m, att[i]);
        float e[K_HOPS + 1];
        float s = 0.f;
        for (int i = 0; i <= K_HOPS; i++) { e[i] = __expf(att[i] - m); s += e[i]; }
        float inv = 1.f / s;
        for (int i = 0; i <= K_HOPS; i++) g_w[i] = e[i] * inv;
    }
}

// ---------------------------------------------------------------------------
// 2) CSR build: degree histogram -> exclusive scan -> scatter src ids
// ---------------------------------------------------------------------------
__global__ void zero_deg_kernel() {
    int i = blockIdx.x * blockDim.x + threadIdx.x;
    if (i < N_NODES) g_deg[i] = 0;
}

__global__ void hist_kernel(const void* __restrict__ ei) {
    int e = blockIdx.x * blockDim.x + threadIdx.x;
    if (e < N_EDGES) {
        int d = load_edge(ei, N_EDGES + e, g_is64);   // edge_index[1] = dst
        atomicAdd(&g_deg[d], 1);
    }
}

// single-block exclusive scan over 50000 ints (chunk-per-thread + Hillis-Steele)
__global__ void scan_kernel() {
    __shared__ int sums[1024];
    const int tid   = threadIdx.x;
    const int chunk = (N_NODES + 1023) / 1024;          // 49
    const int start = tid * chunk;
    const int end   = min(start + chunk, N_NODES);

    int s = 0;
    for (int i = start; i < end; i++) s += g_deg[i];
    sums[tid] = s;
    __syncthreads();

    for (int off = 1; off < 1024; off <<= 1) {
        int v = 0;
        if (tid >= off) v = sums[tid - off];
        __syncthreads();
        sums[tid] += v;
        __syncthreads();
    }

    int run = (tid == 0) ? 0 : sums[tid - 1];           // exclusive base
    for (int i = start; i < end; i++) {
        g_rowptr[i] = run;
        g_cursor[i] = run;
        run += g_deg[i];
    }
    if (tid == 1023) g_rowptr[N_NODES] = sums[1023];    // = N_EDGES
}

__global__ void scatter_kernel(const void* __restrict__ ei) {
    int e = blockIdx.x * blockDim.x + threadIdx.x;
    if (e < N_EDGES) {
        int is64 = g_is64;
        int src = load_edge(ei, e, is64);
        int dst = load_edge(ei, N_EDGES + e, is64);
        int p = atomicAdd(&g_cursor[dst], 1);
        g_col[p] = src;
    }
}

// ---------------------------------------------------------------------------
// 3) out = w[0] * x
// ---------------------------------------------------------------------------
__global__ void init_out_kernel(const float* __restrict__ x, float* __restrict__ out) {
    int i = blockIdx.x * blockDim.x + threadIdx.x;
    if (i < N_NODES * D_FEAT) out[i] = g_w[0] * x[i];
}

// ---------------------------------------------------------------------------
// 4) one propagation hop, warp-per-node, fused weighted accumulation:
//    h_k[n] = sum_{e in CSR(n)} h_{k-1}[col[e]] ;  out[n] += w[k] * h_k[n]
//    Buffers selected inside the kernel from k (h_k lives in g_h0 if k odd,
//    g_h1 if k even). h_0 is the input x.
// ---------------------------------------------------------------------------
__global__ void __launch_bounds__(256)
prop_kernel(const float* __restrict__ x, float* __restrict__ out, int k) {
    const int gwarp = (blockIdx.x * blockDim.x + threadIdx.x) >> 5;
    const int lane  = threadIdx.x & 31;
    if (gwarp >= N_NODES) return;

    const float* hin = (k == 1) ? x : (((k - 1) & 1) ? g_h0 : g_h1);
    float*       hout = (k & 1) ? g_h0 : g_h1;

    const int beg = g_rowptr[gwarp];
    const int end = g_rowptr[gwarp + 1];

    const float4* __restrict__ hi = (const float4*)hin;
    float4 acc = make_float4(0.f, 0.f, 0.f, 0.f);

    for (int e = beg; e < end; e++) {
        int s = g_col[e];
        float4 v = __ldg(&hi[s * 32 + lane]);   // 512B coalesced warp read
        acc.x += v.x; acc.y += v.y; acc.z += v.z; acc.w += v.w;
    }

    ((float4*)hout)[gwarp * 32 + lane] = acc;

    const float w = g_w[k];
    float4* o = (float4*)out;
    float4 ov = o[gwarp * 32 + lane];
    ov.x += w * acc.x; ov.y += w * acc.y; ov.z += w * acc.z; ov.w += w * acc.w;
    o[gwarp * 32 + lane] = ov;
}

// ---------------------------------------------------------------------------
// launch
// ---------------------------------------------------------------------------
extern "C" void kernel_launch(void* const* d_in, const int* in_sizes, int n_in,
                              void* d_out, int out_size) {
    // Identify inputs by element count (robust to metadata ordering):
    //   x = 50000*128 = 6400000, att = 11, edge_index = 2*625000 = 1250000
    const float* x   = nullptr;
    const float* att = nullptr;
    const void*  ei  = nullptr;
    for (int i = 0; i < n_in; i++) {
        if (in_sizes[i] == N_NODES * D_FEAT)      x   = (const float*)d_in[i];
        else if (in_sizes[i] == K_HOPS + 1)       att = (const float*)d_in[i];
        else if (in_sizes[i] == 2 * N_EDGES)      ei  = d_in[i];
    }
    float* out = (float*)d_out;

    detect_dtype_kernel<<<1, 32>>>(ei);
    softmax_att_kernel<<<1, 32>>>(att);

    // CSR build
    zero_deg_kernel<<<(N_NODES + 255) / 256, 256>>>();
    hist_kernel<<<(N_EDGES + 255) / 256, 256>>>(ei);
    scan_kernel<<<1, 1024>>>();
    scatter_kernel<<<(N_EDGES + 255) / 256, 256>>>(ei);

    // out = w0 * x
    init_out_kernel<<<(N_NODES * D_FEAT + 255) / 256, 256>>>(x, out);

    // 10 hops, warp per node
    const int prop_blocks = (N_NODES * 32 + 255) / 256;
    for (int k = 1; k <= K_HOPS; k++) {
        prop_kernel<<<prop_blocks, 256>>>(x, out, k);
    }
}

// round 3
// speedup vs baseline: 1.0021x; 1.0021x over previous
#include <cuda_runtime.h>

#define N_NODES 50000
#define N_EDGES 625000
#define D_FEAT  128
#define K_HOPS  10
#define SZ      (N_NODES * D_FEAT)

// ---------------------------------------------------------------------------
// Scratch (device globals — no allocation allowed anywhere)
// ---------------------------------------------------------------------------
__device__ float g_h[(size_t)K_HOPS * SZ];   // h_k stored at slot k-1 (256 MB)
__device__ int   g_deg[N_NODES];
__device__ int   g_rowptr[N_NODES + 1];
__device__ int   g_cursor[N_NODES];
__device__ int   g_col[N_EDGES];
__device__ float g_w[K_HOPS + 1];
__device__ int   g_is64;

// ---------------------------------------------------------------------------
// 0) dtype detect (int32 vs int64 edge_index) + softmax(att), one tiny kernel
// ---------------------------------------------------------------------------
__global__ void prep_kernel(const void* ei, const float* __restrict__ att) {
    if (threadIdx.x == 0 && blockIdx.x == 0) {
        const long long* p = (const long long*)ei;
        int is64 = 1;
        for (int i = 0; i < 64; i++) {
            long long v = p[i];
            if (v < 0 || v >= (long long)N_NODES) { is64 = 0; break; }
        }
        g_is64 = is64;

        float m = -1e30f;
        for (int i = 0; i <= K_HOPS; i++) m = fmaxf(m, att[i]);
        float e[K_HOPS + 1];
        float s = 0.f;
        for (int i = 0; i <= K_HOPS; i++) { e[i] = __expf(att[i] - m); s += e[i]; }
        float inv = 1.f / s;
        for (int i = 0; i <= K_HOPS; i++) g_w[i] = e[i] * inv;
    }
}

// ---------------------------------------------------------------------------
// CSR build: zero -> histogram -> exclusive scan -> scatter src ids
// ---------------------------------------------------------------------------
__global__ void zero_deg_kernel() {
    int i = blockIdx.x * blockDim.x + threadIdx.x;
    if (i < N_NODES) g_deg[i] = 0;
}

// 2 edges per thread, vectorized index loads
__global__ void hist_kernel(const void* __restrict__ ei) {
    int t = blockIdx.x * blockDim.x + threadIdx.x;
    int e = t * 2;
    if (e >= N_EDGES) return;
    if (g_is64) {
        const longlong2* p = (const longlong2*)((const long long*)ei + N_EDGES);
        longlong2 d = p[t];
        atomicAdd(&g_deg[(int)d.x], 1);
        if (e + 1 < N_EDGES) atomicAdd(&g_deg[(int)d.y], 1);
    } else {
        const int2* p = (const int2*)((const int*)ei + N_EDGES);
        int2 d = p[t];
        atomicAdd(&g_deg[d.x], 1);
        if (e + 1 < N_EDGES) atomicAdd(&g_deg[d.y], 1);
    }
}

// single-block exclusive scan over 50000 ints
__global__ void scan_kernel() {
    __shared__ int sums[1024];
    const int tid   = threadIdx.x;
    const int chunk = (N_NODES + 1023) / 1024;          // 49
    const int start = tid * chunk;
    const int end   = min(start + chunk, N_NODES);

    int s = 0;
    for (int i = start; i < end; i++) s += g_deg[i];
    sums[tid] = s;
    __syncthreads();

    for (int off = 1; off < 1024; off <<= 1) {
        int v = 0;
        if (tid >= off) v = sums[tid - off];
        __syncthreads();
        sums[tid] += v;
        __syncthreads();
    }

    int run = (tid == 0) ? 0 : sums[tid - 1];
    for (int i = start; i < end; i++) {
        g_rowptr[i] = run;
        g_cursor[i] = run;
        run += g_deg[i];
    }
    if (tid == 1023) g_rowptr[N_NODES] = sums[1023];    // = N_EDGES
}

__global__ void scatter_kernel(const void* __restrict__ ei) {
    int t = blockIdx.x * blockDim.x + threadIdx.x;
    int e = t * 2;
    if (e >= N_EDGES) return;
    if (g_is64) {
        const long long* p = (const long long*)ei;
        longlong2 sp = ((const longlong2*)p)[t];
        longlong2 dp = ((const longlong2*)(p + N_EDGES))[t];
        int q0 = atomicAdd(&g_cursor[(int)dp.x], 1);
        g_col[q0] = (int)sp.x;
        if (e + 1 < N_EDGES) {
            int q1 = atomicAdd(&g_cursor[(int)dp.y], 1);
            g_col[q1] = (int)sp.y;
        }
    } else {
        const int* p = (const int*)ei;
        int2 sp = ((const int2*)p)[t];
        int2 dp = ((const int2*)(p + N_EDGES))[t];
        int q0 = atomicAdd(&g_cursor[dp.x], 1);
        g_col[q0] = sp.x;
        if (e + 1 < N_EDGES) {
            int q1 = atomicAdd(&g_cursor[dp.y], 1);
            g_col[q1] = sp.y;
        }
    }
}

// ---------------------------------------------------------------------------
// one propagation hop, warp-per-node:
//   h_k[n] = sum_{e in CSR(n)} h_{k-1}[col[e]]
// h_0 = x (input); h_k stored at g_h + (k-1)*SZ. Unrolled x4 for MLP.
// ---------------------------------------------------------------------------
__global__ void __launch_bounds__(512)
prop_kernel(const float* __restrict__ x, int k) {
    const int gwarp = (blockIdx.x * blockDim.x + threadIdx.x) >> 5;
    const int lane  = threadIdx.x & 31;
    if (gwarp >= N_NODES) return;

    const float* hin  = (k == 1) ? x : (g_h + (size_t)(k - 2) * SZ);
    float*       hout = g_h + (size_t)(k - 1) * SZ;

    const int beg = g_rowptr[gwarp];
    const int end = g_rowptr[gwarp + 1];

    const float4* __restrict__ hi = (const float4*)hin;
    float4 a0 = make_float4(0.f, 0.f, 0.f, 0.f);
    float4 a1 = make_float4(0.f, 0.f, 0.f, 0.f);

    int e = beg;
    for (; e + 4 <= end; e += 4) {
        int s0 = g_col[e + 0];
        int s1 = g_col[e + 1];
        int s2 = g_col[e + 2];
        int s3 = g_col[e + 3];
        float4 v0 = __ldg(&hi[s0 * 32 + lane]);
        float4 v1 = __ldg(&hi[s1 * 32 + lane]);
        float4 v2 = __ldg(&hi[s2 * 32 + lane]);
        float4 v3 = __ldg(&hi[s3 * 32 + lane]);
        a0.x += v0.x; a0.y += v0.y; a0.z += v0.z; a0.w += v0.w;
        a1.x += v1.x; a1.y += v1.y; a1.z += v1.z; a1.w += v1.w;
        a0.x += v2.x; a0.y += v2.y; a0.z += v2.z; a0.w += v2.w;
        a1.x += v3.x; a1.y += v3.y; a1.z += v3.z; a1.w += v3.w;
    }
    for (; e < end; e++) {
        int s = g_col[e];
        float4 v = __ldg(&hi[s * 32 + lane]);
        a0.x += v.x; a0.y += v.y; a0.z += v.z; a0.w += v.w;
    }

    float4 acc = make_float4(a0.x + a1.x, a0.y + a1.y, a0.z + a1.z, a0.w + a1.w);
    ((float4*)hout)[gwarp * 32 + lane] = acc;
}

// ---------------------------------------------------------------------------
// final combine: out = w0*x + sum_k w_k * h_k
// ---------------------------------------------------------------------------
__global__ void __launch_bounds__(256)
combine_kernel(const float* __restrict__ x, float* __restrict__ out) {
    int i = blockIdx.x * blockDim.x + threadIdx.x;   // float4 index
    if (i >= SZ / 4) return;

    float w[K_HOPS + 1];
#pragma unroll
    for (int k = 0; k <= K_HOPS; k++) w[k] = g_w[k];

    float4 xv = ((const float4*)x)[i];
    float4 r;
    r.x = w[0] * xv.x; r.y = w[0] * xv.y; r.z = w[0] * xv.z; r.w = w[0] * xv.w;

#pragma unroll
    for (int k = 1; k <= K_HOPS; k++) {
        float4 hv = __ldg(&((const float4*)(g_h + (size_t)(k - 1) * SZ))[i]);
        r.x += w[k] * hv.x; r.y += w[k] * hv.y;
        r.z += w[k] * hv.z; r.w += w[k] * hv.w;
    }
    ((float4*)out)[i] = r;
}

// ---------------------------------------------------------------------------
// launch
// ---------------------------------------------------------------------------
extern "C" void kernel_launch(void* const* d_in, const int* in_sizes, int n_in,
                              void* d_out, int out_size) {
    const float* x   = nullptr;
    const float* att = nullptr;
    const void*  ei  = nullptr;
    for (int i = 0; i < n_in; i++) {
        if (in_sizes[i] == SZ)               x   = (const float*)d_in[i];
        else if (in_sizes[i] == K_HOPS + 1)  att = (const float*)d_in[i];
        else if (in_sizes[i] == 2 * N_EDGES) ei  = d_in[i];
    }
    float* out = (float*)d_out;

    prep_kernel<<<1, 32>>>(ei, att);

    zero_deg_kernel<<<(N_NODES + 255) / 256, 256>>>();
    hist_kernel<<<((N_EDGES + 1) / 2 + 255) / 256, 256>>>(ei);
    scan_kernel<<<1, 1024>>>();
    scatter_kernel<<<((N_EDGES + 1) / 2 + 255) / 256, 256>>>(ei);

    const int prop_blocks = (N_NODES * 32 + 511) / 512;
    for (int k = 1; k <= K_HOPS; k++) {
        prop_kernel<<<prop_blocks, 512>>>(x, k);
    }

    combine_kernel<<<(SZ / 4 + 255) / 256, 256>>>(x, out);
}

// round 4
// speedup vs baseline: 1.2477x; 1.2450x over previous
#include <cuda_runtime.h>

#define N_NODES 50000
#define N_EDGES 625000
#define D_FEAT  128
#define K_HOPS  10
#define SZ      (N_NODES * D_FEAT)

#define SCAN_TILE 512
#define N_TILES   ((N_NODES + SCAN_TILE - 1) / SCAN_TILE)   // 98

// ---------------------------------------------------------------------------
// Scratch (device globals — no allocation allowed anywhere)
// ---------------------------------------------------------------------------
__device__ float g_h[(size_t)K_HOPS * SZ];   // h_k stored at slot k-1 (256 MB)
__device__ int   g_deg[N_NODES];
__device__ int   g_rowptr[N_NODES + 1];
__device__ int   g_cursor[N_NODES];
__device__ int   g_col[N_EDGES];
__device__ float g_w[K_HOPS + 1];
__device__ int   g_is64;
__device__ int   g_tilesum[N_TILES];
__device__ int   g_tileoff[N_TILES];

// ---------------------------------------------------------------------------
// 0) dtype detect (int32 vs int64 edge_index) + softmax(att)
// ---------------------------------------------------------------------------
__global__ void prep_kernel(const void* ei, const float* __restrict__ att) {
    if (threadIdx.x == 0 && blockIdx.x == 0) {
        const long long* p = (const long long*)ei;
        int is64 = 1;
        for (int i = 0; i < 64; i++) {
            long long v = p[i];
            if (v < 0 || v >= (long long)N_NODES) { is64 = 0; break; }
        }
        g_is64 = is64;

        float m = -1e30f;
        for (int i = 0; i <= K_HOPS; i++) m = fmaxf(m, att[i]);
        float e[K_HOPS + 1];
        float s = 0.f;
        for (int i = 0; i <= K_HOPS; i++) { e[i] = __expf(att[i] - m); s += e[i]; }
        float inv = 1.f / s;
        for (int i = 0; i <= K_HOPS; i++) g_w[i] = e[i] * inv;
    }
}

// ---------------------------------------------------------------------------
// CSR build
// ---------------------------------------------------------------------------
__global__ void zero_deg_kernel() {
    int i = blockIdx.x * blockDim.x + threadIdx.x;
    if (i < N_NODES) g_deg[i] = 0;
}

__global__ void hist_kernel(const void* __restrict__ ei) {
    int t = blockIdx.x * blockDim.x + threadIdx.x;
    int e = t * 2;
    if (e >= N_EDGES) return;
    if (g_is64) {
        const longlong2* p = (const longlong2*)((const long long*)ei + N_EDGES);
        longlong2 d = p[t];
        atomicAdd(&g_deg[(int)d.x], 1);
        if (e + 1 < N_EDGES) atomicAdd(&g_deg[(int)d.y], 1);
    } else {
        const int2* p = (const int2*)((const int*)ei + N_EDGES);
        int2 d = p[t];
        atomicAdd(&g_deg[d.x], 1);
        if (e + 1 < N_EDGES) atomicAdd(&g_deg[d.y], 1);
    }
}

// phase 1: per-tile reduction of deg
__global__ void __launch_bounds__(SCAN_TILE)
scan_reduce_kernel() {
    __shared__ int wsum[SCAN_TILE / 32];
    int i = blockIdx.x * SCAN_TILE + threadIdx.x;
    int v = (i < N_NODES) ? g_deg[i] : 0;
    // warp reduce
    for (int off = 16; off > 0; off >>= 1)
        v += __shfl_down_sync(0xFFFFFFFFu, v, off);
    int wid = threadIdx.x >> 5;
    if ((threadIdx.x & 31) == 0) wsum[wid] = v;
    __syncthreads();
    if (wid == 0) {
        int lane = threadIdx.x & 31;
        int s = (lane < SCAN_TILE / 32) ? wsum[lane] : 0;
        for (int off = 16; off > 0; off >>= 1)
            s += __shfl_down_sync(0xFFFFFFFFu, s, off);
        if (lane == 0) g_tilesum[blockIdx.x] = s;
    }
}

// phase 2: exclusive scan of the 98 tile sums (one small block)
__global__ void scan_tiles_kernel() {
    // 128 threads; warp-shuffle scan over up to 128 values
    __shared__ int wtot[4];
    int tid  = threadIdx.x;
    int lane = tid & 31;
    int wid  = tid >> 5;
    int v = (tid < N_TILES) ? g_tilesum[tid] : 0;
    int incl = v;
    for (int off = 1; off < 32; off <<= 1) {
        int u = __shfl_up_sync(0xFFFFFFFFu, incl, off);
        if (lane >= off) incl += u;
    }
    if (lane == 31) wtot[wid] = incl;
    __syncthreads();
    int base = 0;
    for (int w = 0; w < wid; w++) base += wtot[w];
    int excl = base + incl - v;
    if (tid < N_TILES) g_tileoff[tid] = excl;
    if (tid == N_TILES - 1) g_rowptr[N_NODES] = excl + v;   // = N_EDGES
}

// phase 3: per-tile exclusive scan + tile offset -> rowptr/cursor
__global__ void __launch_bounds__(SCAN_TILE)
scan_final_kernel() {
    __shared__ int wtot[SCAN_TILE / 32];
    int i    = blockIdx.x * SCAN_TILE + threadIdx.x;
    int lane = threadIdx.x & 31;
    int wid  = threadIdx.x >> 5;

    int v = (i < N_NODES) ? g_deg[i] : 0;
    int incl = v;
    for (int off = 1; off < 32; off <<= 1) {
        int u = __shfl_up_sync(0xFFFFFFFFu, incl, off);
        if (lane >= off) incl += u;
    }
    if (lane == 31) wtot[wid] = incl;
    __syncthreads();
    if (wid == 0) {
        int s = (lane < SCAN_TILE / 32) ? wtot[lane] : 0;
        int si = s;
        for (int off = 1; off < 32; off <<= 1) {
            int u = __shfl_up_sync(0xFFFFFFFFu, si, off);
            if (lane >= off) si += u;
        }
        if (lane < SCAN_TILE / 32) wtot[lane] = si - s;   // exclusive warp offsets
    }
    __syncthreads();

    if (i < N_NODES) {
        int excl = g_tileoff[blockIdx.x] + wtot[wid] + incl - v;
        g_rowptr[i] = excl;
        g_cursor[i] = excl;
    }
}

__global__ void scatter_kernel(const void* __restrict__ ei) {
    int t = blockIdx.x * blockDim.x + threadIdx.x;
    int e = t * 2;
    if (e >= N_EDGES) return;
    if (g_is64) {
        const long long* p = (const long long*)ei;
        longlong2 sp = ((const longlong2*)p)[t];
        longlong2 dp = ((const longlong2*)(p + N_EDGES))[t];
        int q0 = atomicAdd(&g_cursor[(int)dp.x], 1);
        g_col[q0] = (int)sp.x;
        if (e + 1 < N_EDGES) {
            int q1 = atomicAdd(&g_cursor[(int)dp.y], 1);
            g_col[q1] = (int)sp.y;
        }
    } else {
        const int* p = (const int*)ei;
        int2 sp = ((const int2*)p)[t];
        int2 dp = ((const int2*)(p + N_EDGES))[t];
        int q0 = atomicAdd(&g_cursor[dp.x], 1);
        g_col[q0] = sp.x;
        if (e + 1 < N_EDGES) {
            int q1 = atomicAdd(&g_cursor[dp.y], 1);
            g_col[q1] = sp.y;
        }
    }
}

// ---------------------------------------------------------------------------
// one propagation hop, warp-per-node
// ---------------------------------------------------------------------------
__global__ void __launch_bounds__(512)
prop_kernel(const float* __restrict__ x, int k) {
    const int gwarp = (blockIdx.x * blockDim.x + threadIdx.x) >> 5;
    const int lane  = threadIdx.x & 31;
    if (gwarp >= N_NODES) return;

    const float* hin  = (k == 1) ? x : (g_h + (size_t)(k - 2) * SZ);
    float*       hout = g_h + (size_t)(k - 1) * SZ;

    const int beg = g_rowptr[gwarp];
    const int end = g_rowptr[gwarp + 1];

    const float4* __restrict__ hi = (const float4*)hin;
    float4 a0 = make_float4(0.f, 0.f, 0.f, 0.f);
    float4 a1 = make_float4(0.f, 0.f, 0.f, 0.f);

    int e = beg;
    for (; e + 4 <= end; e += 4) {
        int s0 = g_col[e + 0];
        int s1 = g_col[e + 1];
        int s2 = g_col[e + 2];
        int s3 = g_col[e + 3];
        float4 v0 = __ldg(&hi[s0 * 32 + lane]);
        float4 v1 = __ldg(&hi[s1 * 32 + lane]);
        float4 v2 = __ldg(&hi[s2 * 32 + lane]);
        float4 v3 = __ldg(&hi[s3 * 32 + lane]);
        a0.x += v0.x; a0.y += v0.y; a0.z += v0.z; a0.w += v0.w;
        a1.x += v1.x; a1.y += v1.y; a1.z += v1.z; a1.w += v1.w;
        a0.x += v2.x; a0.y += v2.y; a0.z += v2.z; a0.w += v2.w;
        a1.x += v3.x; a1.y += v3.y; a1.z += v3.z; a1.w += v3.w;
    }
    for (; e < end; e++) {
        int s = g_col[e];
        float4 v = __ldg(&hi[s * 32 + lane]);
        a0.x += v.x; a0.y += v.y; a0.z += v.z; a0.w += v.w;
    }

    float4 acc = make_float4(a0.x + a1.x, a0.y + a1.y, a0.z + a1.z, a0.w + a1.w);
    ((float4*)hout)[gwarp * 32 + lane] = acc;
}

// ---------------------------------------------------------------------------
// final combine: out = w0*x + sum_k w_k * h_k
// ---------------------------------------------------------------------------
__global__ void __launch_bounds__(256)
combine_kernel(const float* __restrict__ x, float* __restrict__ out) {
    int i = blockIdx.x * blockDim.x + threadIdx.x;   // float4 index
    if (i >= SZ / 4) return;

    float w[K_HOPS + 1];
#pragma unroll
    for (int k = 0; k <= K_HOPS; k++) w[k] = g_w[k];

    float4 xv = ((const float4*)x)[i];
    float4 r;
    r.x = w[0] * xv.x; r.y = w[0] * xv.y; r.z = w[0] * xv.z; r.w = w[0] * xv.w;

#pragma unroll
    for (int k = 1; k <= K_HOPS; k++) {
        float4 hv = __ldg(&((const float4*)(g_h + (size_t)(k - 1) * SZ))[i]);
        r.x += w[k] * hv.x; r.y += w[k] * hv.y;
        r.z += w[k] * hv.z; r.w += w[k] * hv.w;
    }
    ((float4*)out)[i] = r;
}

// ---------------------------------------------------------------------------
// launch
// ---------------------------------------------------------------------------
extern "C" void kernel_launch(void* const* d_in, const int* in_sizes, int n_in,
                              void* d_out, int out_size) {
    const float* x   = nullptr;
    const float* att = nullptr;
    const void*  ei  = nullptr;
    for (int i = 0; i < n_in; i++) {
        if (in_sizes[i] == SZ)               x   = (const float*)d_in[i];
        else if (in_sizes[i] == K_HOPS + 1)  att = (const float*)d_in[i];
        else if (in_sizes[i] == 2 * N_EDGES) ei  = d_in[i];
    }
    float* out = (float*)d_out;

    prep_kernel<<<1, 32>>>(ei, att);

    zero_deg_kernel<<<(N_NODES + 255) / 256, 256>>>();
    hist_kernel<<<((N_EDGES + 1) / 2 + 255) / 256, 256>>>(ei);
    scan_reduce_kernel<<<N_TILES, SCAN_TILE>>>();
    scan_tiles_kernel<<<1, 128>>>();
    scan_final_kernel<<<N_TILES, SCAN_TILE>>>();
    scatter_kernel<<<((N_EDGES + 1) / 2 + 255) / 256, 256>>>(ei);

    const int prop_blocks = (N_NODES * 32 + 511) / 512;
    for (int k = 1; k <= K_HOPS; k++) {
        prop_kernel<<<prop_blocks, 512>>>(x, k);
    }

    combine_kernel<<<(SZ / 4 + 255) / 256, 256>>>(x, out);
}